// round 3
// baseline (speedup 1.0000x reference)
#include <cuda_runtime.h>

// BranchRoute: score = sigmoid(x @ gate_w + gate_b); mask_i = score_i > 0.5
// out = concat(x*m0, x*m1, x*(m0+m1)), each [N, D] fp32.
// sigmoid(z) > 0.5 <=> z > 0, so only the dot-product sign matters.
//
// R3: revert R2's per-row gate __ldg (regressed). Back to register-cached
// gate_w (R1 structure). New: process 2 adjacent rows per iteration with
// loads front-batched (8x LDG.128) and stores grouped by output region
// (8 contiguous STG.128 per region covering 2 rows) for DRAM page locality.
// Persistent grid = 2 blocks/SM exactly; 1 barrier per 2 rows.

#define THREADS 256
#define DIM 4096

__device__ __forceinline__ float4 scale4(float4 v, float f) {
    float4 r;
    r.x = f * v.x; r.y = f * v.y; r.z = f * v.z; r.w = f * v.w;
    return r;
}

__global__ void __launch_bounds__(THREADS, 2)
branch_route_kernel(const float* __restrict__ x,
                    const float* __restrict__ gw,   // [D, 2]
                    const float* __restrict__ gb,   // [2]
                    float* __restrict__ out,        // [3, N, D]
                    int N)
{
    const int t = threadIdx.x;

    // Register cache of this thread's 16 gate_w pairs (columns c*1024 + 4t + j).
    float2 w[16];
#pragma unroll
    for (int c = 0; c < 4; c++) {
#pragma unroll
        for (int j = 0; j < 4; j++) {
            int col = c * 1024 + t * 4 + j;
            w[c * 4 + j] = ((const float2*)gw)[col];
        }
    }
    const float b0 = gb[0];
    const float b1 = gb[1];

    __shared__ float4 red[2][8];   // [parity][warp] = (s00, s01, s10, s11)

    float4* __restrict__ p0 = (float4*)out;
    float4* __restrict__ p1 = (float4*)(out + (size_t)N * DIM);
    float4* __restrict__ pc = (float4*)(out + (size_t)2 * N * DIM);

    const int npairs = N >> 1;
    int parity = 0;
    for (int p = blockIdx.x; p < npairs; p += gridDim.x, parity ^= 1) {
        const size_t base0 = (size_t)(2 * p) * (DIM / 4);   // row 2p, float4 units
        const size_t base1 = base0 + (DIM / 4);             // row 2p+1

        // Front-batched loads: 8 x LDG.128, two adjacent rows.
        const float4* xr = (const float4*)x;
        float4 u[4], v[4];
#pragma unroll
        for (int c = 0; c < 4; c++) u[c] = xr[base0 + c * 256 + t];
#pragma unroll
        for (int c = 0; c < 4; c++) v[c] = xr[base1 + c * 256 + t];

        // Partial dots for both gate columns, both rows.
        float s00 = 0.f, s01 = 0.f, s10 = 0.f, s11 = 0.f;
#pragma unroll
        for (int c = 0; c < 4; c++) {
            const float2 w0 = w[c * 4 + 0], w1 = w[c * 4 + 1];
            const float2 w2 = w[c * 4 + 2], w3 = w[c * 4 + 3];
            s00 = fmaf(u[c].x, w0.x, s00);  s01 = fmaf(u[c].x, w0.y, s01);
            s00 = fmaf(u[c].y, w1.x, s00);  s01 = fmaf(u[c].y, w1.y, s01);
            s00 = fmaf(u[c].z, w2.x, s00);  s01 = fmaf(u[c].z, w2.y, s01);
            s00 = fmaf(u[c].w, w3.x, s00);  s01 = fmaf(u[c].w, w3.y, s01);
            s10 = fmaf(v[c].x, w0.x, s10);  s11 = fmaf(v[c].x, w0.y, s11);
            s10 = fmaf(v[c].y, w1.x, s10);  s11 = fmaf(v[c].y, w1.y, s11);
            s10 = fmaf(v[c].z, w2.x, s10);  s11 = fmaf(v[c].z, w2.y, s11);
            s10 = fmaf(v[c].w, w3.x, s10);  s11 = fmaf(v[c].w, w3.y, s11);
        }

        // Warp butterfly reduce (4 scalars).
#pragma unroll
        for (int o = 16; o > 0; o >>= 1) {
            s00 += __shfl_xor_sync(0xffffffffu, s00, o);
            s01 += __shfl_xor_sync(0xffffffffu, s01, o);
            s10 += __shfl_xor_sync(0xffffffffu, s10, o);
            s11 += __shfl_xor_sync(0xffffffffu, s11, o);
        }
        if ((t & 31) == 0)
            red[parity][t >> 5] = make_float4(s00, s01, s10, s11);
        __syncthreads();   // one barrier per 2 rows (parity double-buffer)

        float d00 = b0, d01 = b1, d10 = b0, d11 = b1;
#pragma unroll
        for (int k = 0; k < 8; k++) {
            float4 r = red[parity][k];
            d00 += r.x; d01 += r.y; d10 += r.z; d11 += r.w;
        }

        const float f00 = d00 > 0.f ? 1.f : 0.f;   // row0 branch0
        const float f01 = d01 > 0.f ? 1.f : 0.f;   // row0 branch1
        const float f10 = d10 > 0.f ? 1.f : 0.f;   // row1 branch0
        const float f11 = d11 > 0.f ? 1.f : 0.f;   // row1 branch1
        const float f0c = f00 + f01;
        const float f1c = f10 + f11;

        // Stores grouped by output region: contiguous 2-row window per region.
#pragma unroll
        for (int c = 0; c < 4; c++) p0[base0 + c * 256 + t] = scale4(u[c], f00);
#pragma unroll
        for (int c = 0; c < 4; c++) p0[base1 + c * 256 + t] = scale4(v[c], f10);
#pragma unroll
        for (int c = 0; c < 4; c++) p1[base0 + c * 256 + t] = scale4(u[c], f01);
#pragma unroll
        for (int c = 0; c < 4; c++) p1[base1 + c * 256 + t] = scale4(v[c], f11);
#pragma unroll
        for (int c = 0; c < 4; c++) pc[base0 + c * 256 + t] = scale4(u[c], f0c);
#pragma unroll
        for (int c = 0; c < 4; c++) pc[base1 + c * 256 + t] = scale4(v[c], f1c);
    }
}

extern "C" void kernel_launch(void* const* d_in, const int* in_sizes, int n_in,
                              void* d_out, int out_size)
{
    const float* x  = (const float*)d_in[0];
    const float* gw = (const float*)d_in[1];
    const float* gb = (const float*)d_in[2];
    float* out = (float*)d_out;

    const int N = in_sizes[0] / DIM;   // 8192

    const int grid = 148 * 2;          // persistent: exactly 2 blocks/SM
    branch_route_kernel<<<grid, THREADS>>>(x, gw, gb, out, N);
}

// round 4
// speedup vs baseline: 1.0936x; 1.0936x over previous
#include <cuda_runtime.h>

// BranchRoute: score = sigmoid(x @ gate_w + gate_b); mask_i = score_i > 0.5
// out = concat(x*m0, x*m1, x*(m0+m1)), each [N, D] fp32.
// sigmoid(z) > 0.5 <=> z > 0, so only the dot-product sign matters.
//
// R4 = R1 (best: 86.5us, DRAM 73.2%) with exactly ONE change:
// output stores use __stcs (evict-first streaming). The 384MiB write stream
// is never re-read; keeping it out of L2 residency lets the LTS drain dirty
// lines promptly and reserves L2 for the read stream.
// Everything else is byte-identical to R1 (register-cached gate_w, 1 row per
// block-iteration, 1184-block persistent grid, 1 barrier/row double-buffered).

#define THREADS 256
#define DIM 4096

__global__ void __launch_bounds__(THREADS)
branch_route_kernel(const float* __restrict__ x,
                    const float* __restrict__ gw,   // [D, 2]
                    const float* __restrict__ gb,   // [2]
                    float* __restrict__ out,        // [3, N, D]
                    int N)
{
    const int t = threadIdx.x;

    // Each thread owns columns {c*1024 + t*4 + j : c in 0..3, j in 0..3}.
    // Load the matching gate_w pairs (w[:,0], w[:,1]) once per block.
    float2 w[16];
#pragma unroll
    for (int c = 0; c < 4; c++) {
#pragma unroll
        for (int j = 0; j < 4; j++) {
            int col = c * 1024 + t * 4 + j;
            w[c * 4 + j] = ((const float2*)gw)[col];
        }
    }
    const float b0 = gb[0];
    const float b1 = gb[1];

    __shared__ float2 red[2][8];   // [parity][warp] partial (s0, s1)

    float* __restrict__ o0 = out;
    float* __restrict__ o1 = out + (size_t)N * DIM;
    float* __restrict__ oc = out + (size_t)2 * N * DIM;

    int parity = 0;
    for (int row = blockIdx.x; row < N; row += gridDim.x, parity ^= 1) {
        const float4* xr = (const float4*)(x + (size_t)row * DIM);

        // Load the row chunk (coalesced float4), keep in registers.
        float4 v[4];
#pragma unroll
        for (int c = 0; c < 4; c++) v[c] = xr[c * 256 + t];

        // Partial dots for both gate columns.
        float s0 = 0.f, s1 = 0.f;
#pragma unroll
        for (int c = 0; c < 4; c++) {
            s0 = fmaf(v[c].x, w[c * 4 + 0].x, s0);
            s1 = fmaf(v[c].x, w[c * 4 + 0].y, s1);
            s0 = fmaf(v[c].y, w[c * 4 + 1].x, s0);
            s1 = fmaf(v[c].y, w[c * 4 + 1].y, s1);
            s0 = fmaf(v[c].z, w[c * 4 + 2].x, s0);
            s1 = fmaf(v[c].z, w[c * 4 + 2].y, s1);
            s0 = fmaf(v[c].w, w[c * 4 + 3].x, s0);
            s1 = fmaf(v[c].w, w[c * 4 + 3].y, s1);
        }

        // Warp butterfly reduce.
#pragma unroll
        for (int o = 16; o > 0; o >>= 1) {
            s0 += __shfl_xor_sync(0xffffffffu, s0, o);
            s1 += __shfl_xor_sync(0xffffffffu, s1, o);
        }
        if ((t & 31) == 0) red[parity][t >> 5] = make_float2(s0, s1);
        __syncthreads();   // single barrier per row (double-buffered shared)

        float d0 = b0, d1 = b1;
#pragma unroll
        for (int k = 0; k < 8; k++) {
            d0 += red[parity][k].x;
            d1 += red[parity][k].y;
        }

        const float f0 = d0 > 0.f ? 1.f : 0.f;
        const float f1 = d1 > 0.f ? 1.f : 0.f;
        const float fc = f0 + f1;

        const size_t base = (size_t)row * (DIM / 4);
        float4* __restrict__ p0 = (float4*)o0 + base;
        float4* __restrict__ p1 = (float4*)o1 + base;
        float4* __restrict__ pc = (float4*)oc + base;

#pragma unroll
        for (int c = 0; c < 4; c++) {
            const int idx = c * 256 + t;
            float4 a, b, s;
            a.x = f0 * v[c].x; a.y = f0 * v[c].y; a.z = f0 * v[c].z; a.w = f0 * v[c].w;
            b.x = f1 * v[c].x; b.y = f1 * v[c].y; b.z = f1 * v[c].z; b.w = f1 * v[c].w;
            s.x = fc * v[c].x; s.y = fc * v[c].y; s.z = fc * v[c].z; s.w = fc * v[c].w;
            __stcs(&p0[idx], a);
            __stcs(&p1[idx], b);
            __stcs(&pc[idx], s);
        }
    }
}

extern "C" void kernel_launch(void* const* d_in, const int* in_sizes, int n_in,
                              void* d_out, int out_size)
{
    const float* x  = (const float*)d_in[0];
    const float* gw = (const float*)d_in[1];
    const float* gb = (const float*)d_in[2];
    float* out = (float*)d_out;

    const int N = in_sizes[0] / DIM;   // 8192

    const int grid = 148 * 8;          // persistent-ish; blocks loop over rows
    branch_route_kernel<<<grid, THREADS>>>(x, gw, gb, out, N);
}